// round 6
// baseline (speedup 1.0000x reference)
#include <cuda_runtime.h>
#include <cuda_bf16.h>
#include <cstdint>
#include <math.h>

#define NROWS 4096
#define DIMS  512
#define TM    128
#define TILES (NROWS / TM)                 // 32
#define NPAIRS (TILES * (TILES + 1) / 2)   // 528
#define KC    128                          // int8 K-chunk = 128 bytes per row
#define NCH   (DIMS / KC)                  // 4

#define QSCALE (127.0f / 8.0f)             // int8 quant: q = round(x * QSCALE)
#define S2     ((8.0f / 127.0f) * (8.0f / 127.0f))

// ---------------- scratch (no dynamic allocation allowed) -------------------
__device__ int   g_Xq[NROWS * DIMS / 4];   // packed int8
__device__ int   g_Yq[NROWS * DIMS / 4];
__device__ float g_shX[NROWS];             // 0.5*||x_i||^2 (exact fp32)
__device__ float g_shY[NROWS];
__device__ float g_rA[NROWS];              // row sums of KX (init 1.0 = diagonal)
__device__ float g_rB[NROWS];
__device__ int   g_flag[TILES * TILES];
__device__ float g_t1corr;
__device__ float g_fsa[16], g_fsb[16], g_fdab[16];

// ---------------- helpers (baseline sm_80+ PTX only) ------------------------
__device__ __forceinline__ uint32_t smem_u32(const void* p) {
    uint32_t a;
    asm("{ .reg .u64 t; cvta.to.shared.u64 t, %1; cvt.u32.u64 %0, t; }" : "=r"(a) : "l"(p));
    return a;
}
__device__ __forceinline__ void ldsm4(uint32_t& r0, uint32_t& r1, uint32_t& r2, uint32_t& r3, uint32_t addr) {
    asm volatile("ldmatrix.sync.aligned.m8n8.x4.shared.b16 {%0,%1,%2,%3}, [%4];"
                 : "=r"(r0), "=r"(r1), "=r"(r2), "=r"(r3) : "r"(addr));
}
// s8 x s8 -> s32, m16n8k32
__device__ __forceinline__ void imma16832(int* c, const uint32_t* a, const uint32_t* b) {
    asm volatile("mma.sync.aligned.m16n8k32.row.col.s32.s8.s8.s32 "
                 "{%0,%1,%2,%3}, {%4,%5,%6,%7}, {%8,%9}, {%0,%1,%2,%3};"
                 : "+r"(c[0]), "+r"(c[1]), "+r"(c[2]), "+r"(c[3])
                 : "r"(a[0]), "r"(a[1]), "r"(a[2]), "r"(a[3]), "r"(b[0]), "r"(b[1]));
}
#define CP16(sm, gm) asm volatile("cp.async.cg.shared.global [%0], [%1], 16;" :: "r"(sm), "l"(gm))
#define CP_COMMIT()  asm volatile("cp.async.commit_group;" ::: "memory")
#define CP_WAIT1()   asm volatile("cp.async.wait_group 1;" ::: "memory")
#define CP_WAIT0()   asm volatile("cp.async.wait_group 0;" ::: "memory")

// SW128 swizzle applied to (row*128 + colbyte), colbyte in [0,128)
__device__ __forceinline__ uint32_t swz(int row, int colbyte) {
    return (uint32_t)(row * 128 + (colbyte ^ ((row & 7) << 4)));
}
__device__ __forceinline__ int q8(float v) {
    int q = __float2int_rn(v * QSCALE);
    return max(-127, min(127, q));
}

// ---------------- SMEM layout for screen kernel -----------------------------
#define SM_A0 0
#define SM_B0 16384
#define SM_A1 32768
#define SM_B1 49152
#define SM_HI 65536
#define SM_HJ (65536 + 512)
#define SM_TOT (65536 + 1024 + 64)

// ---------------------------------------------------------------------------
// Kernel 1: norms (exact fp32) + int8 quantization + accumulator init
// grid 2048 x 256 threads, 2 rows per block
// ---------------------------------------------------------------------------
__global__ __launch_bounds__(256)
void prep_kernel(const float* __restrict__ X, const float* __restrict__ Y) {
    int t = threadIdx.x;
    int row = blockIdx.x * 2 + (t >> 7);
    int tt = t & 127;   // 128 threads per row, 4 floats each
    const float4* xr = reinterpret_cast<const float4*>(X + (size_t)row * DIMS);
    const float4* yr = reinterpret_cast<const float4*>(Y + (size_t)row * DIMS);
    float4 xv = xr[tt], yv = yr[tt];
    float sx = xv.x * xv.x + xv.y * xv.y + xv.z * xv.z + xv.w * xv.w;
    float sy = yv.x * yv.x + yv.y * yv.y + yv.z * yv.z + yv.w * yv.w;
    int px = (q8(xv.x) & 0xff) | ((q8(xv.y) & 0xff) << 8) | ((q8(xv.z) & 0xff) << 16) | ((q8(xv.w) & 0xff) << 24);
    int py = (q8(yv.x) & 0xff) | ((q8(yv.y) & 0xff) << 8) | ((q8(yv.z) & 0xff) << 16) | ((q8(yv.w) & 0xff) << 24);
    g_Xq[(size_t)row * (DIMS / 4) + tt] = px;
    g_Yq[(size_t)row * (DIMS / 4) + tt] = py;
    #pragma unroll
    for (int o = 16; o > 0; o >>= 1) {
        sx += __shfl_xor_sync(0xffffffffu, sx, o);
        sy += __shfl_xor_sync(0xffffffffu, sy, o);
    }
    __shared__ float wx[8], wy[8];
    if ((t & 31) == 0) { wx[t >> 5] = sx; wy[t >> 5] = sy; }
    __syncthreads();
    if (tt == 0) {
        int w0 = (t >> 7) * 4;
        g_shX[row] = 0.5f * (wx[w0] + wx[w0 + 1] + wx[w0 + 2] + wx[w0 + 3]);
        g_shY[row] = 0.5f * (wy[w0] + wy[w0 + 1] + wy[w0 + 2] + wy[w0 + 3]);
        g_rA[row] = 1.0f;
        g_rB[row] = 1.0f;
        if (row < TILES * TILES) g_flag[row] = 0;
        if (row == 0) g_t1corr = 0.f;
    }
}

// ---------------------------------------------------------------------------
// Kernel 2: int8 IMMA screening GEMM over upper-triangular tile pairs.
// grid.x = 2*NPAIRS (matrix 0 = X, 1 = Y), 256 threads = 8 warps (4m x 2n).
// Each warp computes a 32x64 sub-tile of the 128x128 Gram tile.
// s8-k32 fragments share the byte layout of b16-k16, so ldmatrix.b16 works.
// ---------------------------------------------------------------------------
__global__ __launch_bounds__(256, 2)
void screen_kernel() {
    extern __shared__ char smem[];
    uint32_t sb = smem_u32(smem);
    int tid = threadIdx.x;
    int wid = tid >> 5;
    int l = tid & 31;
    int wm = wid >> 1;         // 0..3 : 32-row band
    int wn = wid & 1;          // 0..1 : 64-col band

    int m = (int)blockIdx.x / NPAIRS;
    int p = (int)blockIdx.x % NPAIRS;
    int bi = 0, rem = p;
    while (rem >= TILES - bi) { rem -= TILES - bi; bi++; }
    int bj = bi + rem;
    int ibase = bi * TM, jbase = bj * TM;
    bool diagtile = (bi == bj);

    const char* M = reinterpret_cast<const char*>((m == 0) ? g_Xq : g_Yq);
    const float* SH = (m == 0) ? g_shX : g_shY;

    // copy slice: row cr = tid/2, half ch = tid&1 (64B each), row stride 512B
    int cr = tid >> 1, ch = tid & 1;
    const char* gA = M + (size_t)(ibase + cr) * DIMS + ch * 64;
    const char* gB = M + (size_t)(jbase + cr) * DIMS + ch * 64;
    const uint32_t abuf[2] = {SM_A0, SM_A1};
    const uint32_t bbuf[2] = {SM_B0, SM_B1};

    #pragma unroll
    for (int c = 0; c < 2; c++) {
        #pragma unroll
        for (int i = 0; i < 4; i++) {
            uint32_t so = swz(cr, ch * 64 + i * 16);
            CP16(sb + abuf[c] + so, gA + c * KC + i * 16);
            CP16(sb + bbuf[c] + so, gB + c * KC + i * 16);
        }
        CP_COMMIT();
    }

    int acc[2][8][4];
    #pragma unroll
    for (int mt = 0; mt < 2; mt++)
        #pragma unroll
        for (int nt = 0; nt < 8; nt++)
            #pragma unroll
            for (int q = 0; q < 4; q++) acc[mt][nt][q] = 0;

    #pragma unroll 1
    for (int c = 0; c < NCH; c++) {
        if (c < NCH - 1) CP_WAIT1(); else CP_WAIT0();
        __syncthreads();
        uint32_t ab = sb + abuf[c & 1];
        uint32_t bb = sb + bbuf[c & 1];
        #pragma unroll
        for (int ks = 0; ks < 4; ks++) {          // 4 k-steps of 32 int8 each
            uint32_t a[2][4];
            #pragma unroll
            for (int mt = 0; mt < 2; mt++) {
                int row = wm * 32 + mt * 16 + (l & 15);
                int col = ks * 32 + ((l >> 4) << 4);
                ldsm4(a[mt][0], a[mt][1], a[mt][2], a[mt][3], ab + swz(row, col));
            }
            #pragma unroll
            for (int np = 0; np < 4; np++) {
                int row = wn * 64 + np * 16 + (l & 7) + ((l >> 4) & 1) * 8;
                int col = ks * 32 + ((l >> 3) & 1) * 16;
                uint32_t b[4];
                ldsm4(b[0], b[1], b[2], b[3], bb + swz(row, col));
                #pragma unroll
                for (int mt = 0; mt < 2; mt++) {
                    imma16832(acc[mt][np * 2],     a[mt], b);
                    imma16832(acc[mt][np * 2 + 1], a[mt], b + 2);
                }
            }
        }
        __syncthreads();
        if (c + 2 < NCH) {
            #pragma unroll
            for (int i = 0; i < 4; i++) {
                uint32_t so = swz(cr, ch * 64 + i * 16);
                CP16(sb + abuf[c & 1] + so, gA + (c + 2) * KC + i * 16);
                CP16(sb + bbuf[c & 1] + so, gB + (c + 2) * KC + i * 16);
            }
            CP_COMMIT();
        }
    }

    float* hiS = reinterpret_cast<float*>(smem + SM_HI);
    float* hjS = reinterpret_cast<float*>(smem + SM_HJ);
    if (tid < TM) {
        hiS[tid] = SH[ibase + tid];
        hjS[tid] = SH[jbase + tid];
    }
    __syncthreads();

    // epilogue: arg ~= s^2*dot_q - hi - hj ; tile max excluding the true diagonal
    float mx = -1e30f;
    #pragma unroll
    for (int mt = 0; mt < 2; mt++) {
        int lr0 = wm * 32 + mt * 16 + (l >> 2);
        #pragma unroll
        for (int nt = 0; nt < 8; nt++) {
            int lc0 = wn * 64 + nt * 8 + (l & 3) * 2;
            #pragma unroll
            for (int q = 0; q < 4; q++) {
                int lr = lr0 + ((q >> 1) << 3);
                int lc = lc0 + (q & 1);
                float arg = (float)acc[mt][nt][q] * S2 - hiS[lr] - hjS[lc];
                bool isdiag = diagtile && (lr == lc);
                if (!isdiag) mx = fmaxf(mx, arg);
            }
        }
    }
    #pragma unroll
    for (int o = 16; o > 0; o >>= 1) mx = fmaxf(mx, __shfl_xor_sync(0xffffffffu, mx, o));
    __shared__ float wmx[8];
    if (l == 0) wmx[wid] = mx;
    __syncthreads();
    if (tid == 0) {
        float bm = wmx[0];
        #pragma unroll
        for (int w = 1; w < 8; w++) bm = fmaxf(bm, wmx[w]);
        // int8 quant error in arg bounded by ~33; fp32 survivors (incl.
        // subnormals) need true arg > -104  =>  flag if quantized arg > -140.
        if (bm > -140.f) g_flag[bi * TILES + bj] = 1;
    }
}

// ---------------------------------------------------------------------------
// Kernel 3: exact fp32 fallback for flagged tiles (expected: none flagged)
// ---------------------------------------------------------------------------
__global__ void fallback_kernel(const float* __restrict__ X, const float* __restrict__ Y) {
    int p = (int)blockIdx.x;
    int bi = 0, rem = p;
    while (rem >= TILES - bi) { rem -= TILES - bi; bi++; }
    int bj = bi + rem;
    if (g_flag[bi * TILES + bj] == 0) return;

    int ibase = bi * TM, jbase = bj * TM;
    for (int e = threadIdx.x; e < TM * TM; e += blockDim.x) {
        int li = e >> 7, lj = e & 127;
        int gi = ibase + li, gj = jbase + lj;
        if (gi >= gj) continue;   // strict upper only (diag handled analytically)
        const float4* xi = reinterpret_cast<const float4*>(X + (size_t)gi * DIMS);
        const float4* xj = reinterpret_cast<const float4*>(X + (size_t)gj * DIMS);
        const float4* yi = reinterpret_cast<const float4*>(Y + (size_t)gi * DIMS);
        const float4* yj = reinterpret_cast<const float4*>(Y + (size_t)gj * DIMS);
        float dx = 0.f, dy = 0.f;
        for (int k = 0; k < DIMS / 4; k++) {
            float4 a = xi[k], b = xj[k], c = yi[k], d = yj[k];
            dx += a.x * b.x + a.y * b.y + a.z * b.z + a.w * b.w;
            dy += c.x * d.x + c.y * d.y + c.z * d.z + c.w * d.w;
        }
        float ax = dx - g_shX[gi] - g_shX[gj];
        float ay = dy - g_shY[gi] - g_shY[gj];
        float ex = (ax > -87.f) ? expf(ax) : 0.f;
        float ey = (ay > -87.f) ? expf(ay) : 0.f;
        if (ex != 0.f) { atomicAdd(&g_rA[gi], ex); atomicAdd(&g_rA[gj], ex); }
        if (ey != 0.f) { atomicAdd(&g_rB[gi], ey); atomicAdd(&g_rB[gj], ey); }
        if (ex != 0.f && ey != 0.f) atomicAdd(&g_t1corr, 2.f * ex * ey);
    }
}

// ---------------------------------------------------------------------------
// Kernel 4a: parallel partial reduction over rows (16 blocks x 256 threads)
// ---------------------------------------------------------------------------
__global__ __launch_bounds__(256)
void final1_kernel() {
    int b = blockIdx.x, t = threadIdx.x;
    int i = b * 256 + t;
    float a = g_rA[i], bb = g_rB[i];
    float sa = a, sb = bb, dab = a * bb;
    #pragma unroll
    for (int o = 16; o > 0; o >>= 1) {
        sa += __shfl_xor_sync(0xffffffffu, sa, o);
        sb += __shfl_xor_sync(0xffffffffu, sb, o);
        dab += __shfl_xor_sync(0xffffffffu, dab, o);
    }
    __shared__ float s1[8], s2[8], s3[8];
    if ((t & 31) == 0) { int w = t >> 5; s1[w] = sa; s2[w] = sb; s3[w] = dab; }
    __syncthreads();
    if (t == 0) {
        float SA = 0.f, SB = 0.f, DAB = 0.f;
        #pragma unroll
        for (int w = 0; w < 8; w++) { SA += s1[w]; SB += s2[w]; DAB += s3[w]; }
        g_fsa[b] = SA; g_fsb[b] = SB; g_fdab[b] = DAB;
    }
}

// ---------------------------------------------------------------------------
// Kernel 4b: final combine (1 block, 32 threads)
// S = T1 - (2/n)*sum(rA.*rB) + (sum rA)(sum rB)/n^2 ; T1 = n + t1corr
// ---------------------------------------------------------------------------
__global__ void final2_kernel(float* __restrict__ out) {
    int t = threadIdx.x;
    float sa = (t < 16) ? g_fsa[t] : 0.f;
    float sb = (t < 16) ? g_fsb[t] : 0.f;
    float dab = (t < 16) ? g_fdab[t] : 0.f;
    #pragma unroll
    for (int o = 8; o > 0; o >>= 1) {
        sa += __shfl_xor_sync(0xffffffffu, sa, o);
        sb += __shfl_xor_sync(0xffffffffu, sb, o);
        dab += __shfl_xor_sync(0xffffffffu, dab, o);
    }
    if (t == 0) {
        float n = (float)NROWS;
        float T1 = n + g_t1corr;
        float S = T1 - 2.f * dab / n + sa * sb / (n * n);
        out[0] = S / ((n - 1.f) * (n - 1.f));
    }
}

// ---------------------------------------------------------------------------
extern "C" void kernel_launch(void* const* d_in, const int* in_sizes, int n_in,
                              void* d_out, int out_size) {
    const float* X = (const float*)d_in[0];
    const float* Y = (const float*)d_in[1];
    float* out = (float*)d_out;
    (void)in_sizes; (void)n_in; (void)out_size;

    cudaFuncSetAttribute(screen_kernel, cudaFuncAttributeMaxDynamicSharedMemorySize, SM_TOT);

    prep_kernel<<<NROWS / 2, 256>>>(X, Y);
    screen_kernel<<<2 * NPAIRS, 256, SM_TOT>>>();
    fallback_kernel<<<NPAIRS, 256>>>(X, Y);
    final1_kernel<<<16, 256>>>();
    final2_kernel<<<1, 32>>>(out);
}

// round 10
// speedup vs baseline: 2.7534x; 2.7534x over previous
#include <cuda_runtime.h>
#include <cuda_bf16.h>
#include <cstdint>
#include <math.h>

#define NROWS 4096
#define DIMS  512
#define DIMS_S 256                         // screening dims (certified lower bound)
#define TM    128
#define TILES (NROWS / TM)                 // 32
#define NPAIRS (TILES * (TILES + 1) / 2)   // 528
#define KC    64                           // bf16 K-chunk = 128 bytes per row
#define NCH   (DIMS_S / KC)                // 4

// ---------------- scratch (no dynamic allocation allowed) -------------------
__device__ __nv_bfloat16 g_Xb[NROWS * DIMS_S];
__device__ __nv_bfloat16 g_Yb[NROWS * DIMS_S];
__device__ float g_shX[NROWS];    // 0.5*||x_i||^2 over all 512 dims (exact)
__device__ float g_shY[NROWS];
__device__ float g_shXs[NROWS];   // 0.5*||x_i[0:256]||^2 (screen bound)
__device__ float g_shYs[NROWS];
__device__ float g_rA[NROWS];     // row sums of KX (init 1.0 = diagonal)
__device__ float g_rB[NROWS];
__device__ int   g_flag[TILES * TILES];
__device__ float g_t1corr;
__device__ float g_fsa[16], g_fsb[16], g_fdab[16];

// ---------------- helpers (baseline sm_80+ PTX only) ------------------------
__device__ __forceinline__ uint32_t smem_u32(const void* p) {
    uint32_t a;
    asm("{ .reg .u64 t; cvta.to.shared.u64 t, %1; cvt.u32.u64 %0, t; }" : "=r"(a) : "l"(p));
    return a;
}
__device__ __forceinline__ void ldsm4(uint32_t& r0, uint32_t& r1, uint32_t& r2, uint32_t& r3, uint32_t addr) {
    asm volatile("ldmatrix.sync.aligned.m8n8.x4.shared.b16 {%0,%1,%2,%3}, [%4];"
                 : "=r"(r0), "=r"(r1), "=r"(r2), "=r"(r3) : "r"(addr));
}
__device__ __forceinline__ void mma16816(float* c, const uint32_t* a, const uint32_t* b) {
    asm volatile("mma.sync.aligned.m16n8k16.row.col.f32.bf16.bf16.f32 "
                 "{%0,%1,%2,%3}, {%4,%5,%6,%7}, {%8,%9}, {%0,%1,%2,%3};"
                 : "+f"(c[0]), "+f"(c[1]), "+f"(c[2]), "+f"(c[3])
                 : "r"(a[0]), "r"(a[1]), "r"(a[2]), "r"(a[3]), "r"(b[0]), "r"(b[1]));
}
#define CP16(sm, gm) asm volatile("cp.async.cg.shared.global [%0], [%1], 16;" :: "r"(sm), "l"(gm))
#define CP_COMMIT()  asm volatile("cp.async.commit_group;" ::: "memory")
#define CP_WAIT1()   asm volatile("cp.async.wait_group 1;" ::: "memory")
#define CP_WAIT0()   asm volatile("cp.async.wait_group 0;" ::: "memory")

// SW128 swizzle applied to (row*128 + colbyte), colbyte in [0,128)
__device__ __forceinline__ uint32_t swz(int row, int colbyte) {
    return (uint32_t)(row * 128 + (colbyte ^ ((row & 7) << 4)));
}

// ---------------- SMEM layout for screen kernel -----------------------------
#define SM_A0 0
#define SM_B0 16384
#define SM_A1 32768
#define SM_B1 49152
#define SM_HI 65536
#define SM_HJ (65536 + 512)
#define SM_TOT (65536 + 1024 + 64)

// ---------------------------------------------------------------------------
// Kernel 1: full norms (exact fp32) + sub-norms + bf16 of first 256 dims
// grid 2048 x 256 threads, 2 rows per block (128 threads per row)
// ---------------------------------------------------------------------------
__global__ __launch_bounds__(256)
void prep_kernel(const float* __restrict__ X, const float* __restrict__ Y) {
    int t = threadIdx.x;
    int row = blockIdx.x * 2 + (t >> 7);
    int tt = t & 127;   // 128 threads per row, 4 floats each (512 dims)
    const float4* xr = reinterpret_cast<const float4*>(X + (size_t)row * DIMS);
    const float4* yr = reinterpret_cast<const float4*>(Y + (size_t)row * DIMS);
    float4 xv = xr[tt], yv = yr[tt];
    float sx = xv.x * xv.x + xv.y * xv.y + xv.z * xv.z + xv.w * xv.w;
    float sy = yv.x * yv.x + yv.y * yv.y + yv.z * yv.z + yv.w * yv.w;
    float sxs = (tt < 64) ? sx : 0.f;   // first 256 dims
    float sys = (tt < 64) ? sy : 0.f;
    if (tt < 64) {   // bf16 store of screening dims
        __nv_bfloat162* xo = reinterpret_cast<__nv_bfloat162*>(g_Xb + (size_t)row * DIMS_S);
        __nv_bfloat162* yo = reinterpret_cast<__nv_bfloat162*>(g_Yb + (size_t)row * DIMS_S);
        xo[tt * 2 + 0] = __floats2bfloat162_rn(xv.x, xv.y);
        xo[tt * 2 + 1] = __floats2bfloat162_rn(xv.z, xv.w);
        yo[tt * 2 + 0] = __floats2bfloat162_rn(yv.x, yv.y);
        yo[tt * 2 + 1] = __floats2bfloat162_rn(yv.z, yv.w);
    }
    #pragma unroll
    for (int o = 16; o > 0; o >>= 1) {
        sx  += __shfl_xor_sync(0xffffffffu, sx,  o);
        sy  += __shfl_xor_sync(0xffffffffu, sy,  o);
        sxs += __shfl_xor_sync(0xffffffffu, sxs, o);
        sys += __shfl_xor_sync(0xffffffffu, sys, o);
    }
    __shared__ float wx[8], wy[8], wxs[8], wys[8];
    if ((t & 31) == 0) {
        int w = t >> 5;
        wx[w] = sx; wy[w] = sy; wxs[w] = sxs; wys[w] = sys;
    }
    __syncthreads();
    if (tt == 0) {
        int w0 = (t >> 7) * 4;
        g_shX[row]  = 0.5f * (wx[w0] + wx[w0 + 1] + wx[w0 + 2] + wx[w0 + 3]);
        g_shY[row]  = 0.5f * (wy[w0] + wy[w0 + 1] + wy[w0 + 2] + wy[w0 + 3]);
        g_shXs[row] = 0.5f * (wxs[w0] + wxs[w0 + 1] + wxs[w0 + 2] + wxs[w0 + 3]);
        g_shYs[row] = 0.5f * (wys[w0] + wys[w0 + 1] + wys[w0 + 2] + wys[w0 + 3]);
        g_rA[row] = 1.0f;
        g_rB[row] = 1.0f;
        if (row < TILES * TILES) g_flag[row] = 0;
        if (row == 0) g_t1corr = 0.f;
    }
}

// ---------------------------------------------------------------------------
// Kernel 2: bf16 mma.sync screening GEMM over first 256 dims.
// d^2_full >= d^2_sub exactly, so arg_sub <= -115 certifies the pair dead.
// grid.x = 2*NPAIRS (matrix 0 = X, 1 = Y), 256 threads = 8 warps (4m x 2n).
// ---------------------------------------------------------------------------
__global__ __launch_bounds__(256, 2)
void screen_kernel() {
    extern __shared__ char smem[];
    uint32_t sb = smem_u32(smem);
    int tid = threadIdx.x;
    int wid = tid >> 5;
    int l = tid & 31;
    int wm = wid >> 1;         // 0..3 : 32-row band
    int wn = wid & 1;          // 0..1 : 64-col band

    int m = (int)blockIdx.x / NPAIRS;
    int p = (int)blockIdx.x % NPAIRS;
    int bi = 0, rem = p;
    while (rem >= TILES - bi) { rem -= TILES - bi; bi++; }
    int bj = bi + rem;
    int ibase = bi * TM, jbase = bj * TM;
    bool diagtile = (bi == bj);

    const __nv_bfloat16* M = (m == 0) ? g_Xb : g_Yb;
    const float* SH = (m == 0) ? g_shXs : g_shYs;

    // copy slice: row cr = tid/2, half ch = tid&1 (64B each); row stride 512B
    int cr = tid >> 1, ch = tid & 1;
    const char* gA = reinterpret_cast<const char*>(M) + (size_t)(ibase + cr) * (DIMS_S * 2) + ch * 64;
    const char* gB = reinterpret_cast<const char*>(M) + (size_t)(jbase + cr) * (DIMS_S * 2) + ch * 64;
    const uint32_t abuf[2] = {SM_A0, SM_A1};
    const uint32_t bbuf[2] = {SM_B0, SM_B1};

    #pragma unroll
    for (int c = 0; c < 2; c++) {
        #pragma unroll
        for (int i = 0; i < 4; i++) {
            uint32_t so = swz(cr, ch * 64 + i * 16);
            CP16(sb + abuf[c] + so, gA + c * 128 + i * 16);
            CP16(sb + bbuf[c] + so, gB + c * 128 + i * 16);
        }
        CP_COMMIT();
    }

    float acc[2][8][4];
    #pragma unroll
    for (int mt = 0; mt < 2; mt++)
        #pragma unroll
        for (int nt = 0; nt < 8; nt++)
            #pragma unroll
            for (int q = 0; q < 4; q++) acc[mt][nt][q] = 0.f;

    #pragma unroll 1
    for (int c = 0; c < NCH; c++) {
        if (c < NCH - 1) CP_WAIT1(); else CP_WAIT0();
        __syncthreads();
        uint32_t ab = sb + abuf[c & 1];
        uint32_t bb = sb + bbuf[c & 1];
        #pragma unroll
        for (int ks = 0; ks < 4; ks++) {
            uint32_t a[2][4];
            #pragma unroll
            for (int mt = 0; mt < 2; mt++) {
                int row = wm * 32 + mt * 16 + (l & 15);
                int col = ks * 32 + ((l >> 4) << 4);
                ldsm4(a[mt][0], a[mt][1], a[mt][2], a[mt][3], ab + swz(row, col));
            }
            #pragma unroll
            for (int np = 0; np < 4; np++) {
                int row = wn * 64 + np * 16 + (l & 7) + ((l >> 4) & 1) * 8;
                int col = ks * 32 + ((l >> 3) & 1) * 16;
                uint32_t b[4];
                ldsm4(b[0], b[1], b[2], b[3], bb + swz(row, col));
                #pragma unroll
                for (int mt = 0; mt < 2; mt++) {
                    mma16816(acc[mt][np * 2],     a[mt], b);
                    mma16816(acc[mt][np * 2 + 1], a[mt], b + 2);
                }
            }
        }
        __syncthreads();
        if (c + 2 < NCH) {
            #pragma unroll
            for (int i = 0; i < 4; i++) {
                uint32_t so = swz(cr, ch * 64 + i * 16);
                CP16(sb + abuf[c & 1] + so, gA + (c + 2) * 128 + i * 16);
                CP16(sb + bbuf[c & 1] + so, gB + (c + 2) * 128 + i * 16);
            }
            CP_COMMIT();
        }
    }

    float* hiS = reinterpret_cast<float*>(smem + SM_HI);
    float* hjS = reinterpret_cast<float*>(smem + SM_HJ);
    if (tid < TM) {
        hiS[tid] = SH[ibase + tid];
        hjS[tid] = SH[jbase + tid];
    }
    __syncthreads();

    // epilogue: arg_sub = dot_sub - hi_sub - hj_sub = -0.5*d^2_sub (+- bf16 err)
    float mx = -1e30f;
    #pragma unroll
    for (int mt = 0; mt < 2; mt++) {
        int lr0 = wm * 32 + mt * 16 + (l >> 2);
        #pragma unroll
        for (int nt = 0; nt < 8; nt++) {
            int lc0 = wn * 64 + nt * 8 + (l & 3) * 2;
            #pragma unroll
            for (int q = 0; q < 4; q++) {
                int lr = lr0 + ((q >> 1) << 3);
                int lc = lc0 + (q & 1);
                float arg = acc[mt][nt][q] - hiS[lr] - hjS[lc];
                bool isdiag = diagtile && (lr == lc);
                if (!isdiag) mx = fmaxf(mx, arg);
            }
        }
    }
    #pragma unroll
    for (int o = 16; o > 0; o >>= 1) mx = fmaxf(mx, __shfl_xor_sync(0xffffffffu, mx, o));
    __shared__ float wmx[8];
    if (l == 0) wmx[wid] = mx;
    __syncthreads();
    if (tid == 0) {
        float bm = wmx[0];
        #pragma unroll
        for (int w = 1; w < 8; w++) bm = fmaxf(bm, wmx[w]);
        // survivor needs arg_full > -104 (subnormal floor); arg_sub >= arg_full
        // minus nothing (d^2 monotone in dims); bf16 error <= ~3 => flag at -115.
        if (bm > -115.f) g_flag[bi * TILES + bj] = 1;
    }
}

// ---------------------------------------------------------------------------
// Kernel 3: exact fp32 fallback for flagged tiles (expected: none flagged)
// ---------------------------------------------------------------------------
__global__ void fallback_kernel(const float* __restrict__ X, const float* __restrict__ Y) {
    int p = (int)blockIdx.x;
    int bi = 0, rem = p;
    while (rem >= TILES - bi) { rem -= TILES - bi; bi++; }
    int bj = bi + rem;
    if (g_flag[bi * TILES + bj] == 0) return;

    int ibase = bi * TM, jbase = bj * TM;
    for (int e = threadIdx.x; e < TM * TM; e += blockDim.x) {
        int li = e >> 7, lj = e & 127;
        int gi = ibase + li, gj = jbase + lj;
        if (gi >= gj) continue;   // strict upper only (diag handled analytically)
        const float4* xi = reinterpret_cast<const float4*>(X + (size_t)gi * DIMS);
        const float4* xj = reinterpret_cast<const float4*>(X + (size_t)gj * DIMS);
        const float4* yi = reinterpret_cast<const float4*>(Y + (size_t)gi * DIMS);
        const float4* yj = reinterpret_cast<const float4*>(Y + (size_t)gj * DIMS);
        float dx = 0.f, dy = 0.f;
        for (int k = 0; k < DIMS / 4; k++) {
            float4 a = xi[k], b = xj[k], c = yi[k], d = yj[k];
            dx += a.x * b.x + a.y * b.y + a.z * b.z + a.w * b.w;
            dy += c.x * d.x + c.y * d.y + c.z * d.z + c.w * d.w;
        }
        float ax = dx - g_shX[gi] - g_shX[gj];
        float ay = dy - g_shY[gi] - g_shY[gj];
        float ex = (ax > -87.f) ? expf(ax) : 0.f;
        float ey = (ay > -87.f) ? expf(ay) : 0.f;
        if (ex != 0.f) { atomicAdd(&g_rA[gi], ex); atomicAdd(&g_rA[gj], ex); }
        if (ey != 0.f) { atomicAdd(&g_rB[gi], ey); atomicAdd(&g_rB[gj], ey); }
        if (ex != 0.f && ey != 0.f) atomicAdd(&g_t1corr, 2.f * ex * ey);
    }
}

// ---------------------------------------------------------------------------
// Kernel 4a: parallel partial reduction over rows (16 blocks x 256 threads)
// ---------------------------------------------------------------------------
__global__ __launch_bounds__(256)
void final1_kernel() {
    int b = blockIdx.x, t = threadIdx.x;
    int i = b * 256 + t;
    float a = g_rA[i], bb = g_rB[i];
    float sa = a, sb = bb, dab = a * bb;
    #pragma unroll
    for (int o = 16; o > 0; o >>= 1) {
        sa += __shfl_xor_sync(0xffffffffu, sa, o);
        sb += __shfl_xor_sync(0xffffffffu, sb, o);
        dab += __shfl_xor_sync(0xffffffffu, dab, o);
    }
    __shared__ float s1[8], s2[8], s3[8];
    if ((t & 31) == 0) { int w = t >> 5; s1[w] = sa; s2[w] = sb; s3[w] = dab; }
    __syncthreads();
    if (t == 0) {
        float SA = 0.f, SB = 0.f, DAB = 0.f;
        #pragma unroll
        for (int w = 0; w < 8; w++) { SA += s1[w]; SB += s2[w]; DAB += s3[w]; }
        g_fsa[b] = SA; g_fsb[b] = SB; g_fdab[b] = DAB;
    }
}

// ---------------------------------------------------------------------------
// Kernel 4b: final combine (1 block, 32 threads)
// S = T1 - (2/n)*sum(rA.*rB) + (sum rA)(sum rB)/n^2 ; T1 = n + t1corr
// ---------------------------------------------------------------------------
__global__ void final2_kernel(float* __restrict__ out) {
    int t = threadIdx.x;
    float sa = (t < 16) ? g_fsa[t] : 0.f;
    float sb = (t < 16) ? g_fsb[t] : 0.f;
    float dab = (t < 16) ? g_fdab[t] : 0.f;
    #pragma unroll
    for (int o = 8; o > 0; o >>= 1) {
        sa += __shfl_xor_sync(0xffffffffu, sa, o);
        sb += __shfl_xor_sync(0xffffffffu, sb, o);
        dab += __shfl_xor_sync(0xffffffffu, dab, o);
    }
    if (t == 0) {
        float n = (float)NROWS;
        float T1 = n + g_t1corr;
        float S = T1 - 2.f * dab / n + sa * sb / (n * n);
        out[0] = S / ((n - 1.f) * (n - 1.f));
    }
}

// ---------------------------------------------------------------------------
extern "C" void kernel_launch(void* const* d_in, const int* in_sizes, int n_in,
                              void* d_out, int out_size) {
    const float* X = (const float*)d_in[0];
    const float* Y = (const float*)d_in[1];
    float* out = (float*)d_out;
    (void)in_sizes; (void)n_in; (void)out_size;

    cudaFuncSetAttribute(screen_kernel, cudaFuncAttributeMaxDynamicSharedMemorySize, SM_TOT);

    prep_kernel<<<NROWS / 2, 256>>>(X, Y);
    screen_kernel<<<2 * NPAIRS, 256, SM_TOT>>>();
    fallback_kernel<<<NPAIRS, 256>>>(X, Y);
    final1_kernel<<<16, 256>>>();
    final2_kernel<<<1, 32>>>(out);
}